// round 8
// baseline (speedup 1.0000x reference)
#include <cuda_runtime.h>
#include <math.h>

// Problem constants
#define B 32
#define L 4096
#define H 1024
#define GRID 148            // == SM count -> every block resident in wave 1
#define NTH 1024
#define NWARPS (GRID * 32)  // 4736 warps; 4736 % 32 == 0 -> warp keeps fixed b
#define NGRP (L / 4)        // 1024 groups of 4 rows per b
#define TOTGRP (B * NGRP)   // 32768

// Scratch (device globals — no allocation allowed)
__device__ float    g_vpart[32][B * H];    // 4 MB GEMM partials
__device__ float    g_v[B * H];            // 128 KB  v = hid @ W
__device__ float    g_energies[B * L];     // 512 KB
__device__ float2   g_cstats[B * NGRP];    // per-group (max, sumexp), keyed -> deterministic
__device__ unsigned g_barctr[3];           // monotonic grid-barrier counters (never reset)

// Grid barrier: monotonic counter, safe across graph replays (no reset).
__device__ __forceinline__ void grid_barrier(int site)
{
    __syncthreads();
    if (threadIdx.x == 0) {
        __threadfence();
        unsigned t = atomicAdd(&g_barctr[site], 1u);
        unsigned target = (t / GRID + 1u) * GRID;
        unsigned v;
        do {
            asm volatile("ld.acquire.gpu.u32 %0, [%1];"
                         : "=r"(v) : "l"(&g_barctr[site]));
        } while (v < target);
    }
    __syncthreads();
}

extern __shared__ float4 sv[];   // dynamic smem: 8192 float4 = 128 KB = all 32 v rows

__global__ void __launch_bounds__(NTH, 1)
k_fused(const float* __restrict__ hid, const float* __restrict__ enc,
        const float* __restrict__ W, float* __restrict__ out)
{
    __shared__ float  sh_hid[32][33];   // P0 hid tile (padded)
    __shared__ float2 s_st[NGRP];       // P2 stat tree (8 KB)

    const int tid  = threadIdx.x;
    const int blk  = blockIdx.x;
    const int wid  = tid >> 5;
    const int lane = tid & 31;

    // ---------------- P0a: GEMM partials ----------------------------------
    if (blk < 128) {
        const int g0 = (blk & 31) * 32;                 // g-chunk
        const int h  = (blk >> 5) * 256 + (tid & 255);  // h quarter
        const int b0 = (tid >> 8) * 8;                  // 8-b subgroup

        { // stage hid[b][g0..g0+32] tile (1024 elems, one per thread)
            int bb = tid >> 5, gi = tid & 31;
            sh_hid[bb][gi] = hid[bb * H + g0 + gi];
        }
        __syncthreads();

        float acc[8];
#pragma unroll
        for (int k = 0; k < 8; k++) acc[k] = 0.f;

#pragma unroll 4
        for (int gi = 0; gi < 32; gi++) {
            const float w = W[(size_t)(g0 + gi) * H + h];
#pragma unroll
            for (int k = 0; k < 8; k++)
                acc[k] = fmaf(sh_hid[b0 + k][gi], w, acc[k]);
        }
#pragma unroll
        for (int k = 0; k < 8; k++)
            g_vpart[blk & 31][(size_t)(b0 + k) * H + h] = acc[k];
    }
    grid_barrier(0);

    // ---------------- P0b: deterministic reduce to g_v --------------------
    if (blk < 32) {
        const int i = blk * NTH + tid;
        float s = 0.f;
#pragma unroll
        for (int gc = 0; gc < 32; gc++) s += g_vpart[gc][i];
        g_v[i] = s;
    }
    grid_barrier(1);

    // ---------------- P0c: stage ALL v (128 KB) into smem -----------------
    const float4* gv4 = reinterpret_cast<const float4*>(g_v);
#pragma unroll
    for (int k = 0; k < 8; k++) sv[tid + NTH * k] = gv4[tid + NTH * k];
    __syncthreads();

    // ---------------- P1: energies + per-group softmax stats --------------
    // Static assignment: group g = gwarp + k*NWARPS. NWARPS % 32 == 0, so
    // b = g & 31 == wid stays fixed per warp. 4 independent rows per group
    // -> 32 LDG.128 in flight (R2-grade MLP). No atomics anywhere.
    {
        const int gwarp = blk * 32 + wid;
        const int b     = wid;                  // == gwarp & 31
        const float4* svb = sv + b * 256;

        for (int g = gwarp; g < TOTGRP; g += NWARPS) {
            const int lgrp = g >> 5;
            const int l0   = lgrp * 4;

            float acc[4] = {0.f, 0.f, 0.f, 0.f};
#pragma unroll
            for (int j = 0; j < 4; j++) {
                const float4* e4 = reinterpret_cast<const float4*>(
                    enc + ((size_t)(l0 + j) * B + b) * H);
#pragma unroll
                for (int i = 0; i < 8; i++) {
                    float4 a = e4[lane + 32 * i];
                    float4 v = svb[lane + 32 * i];
                    acc[j] = fmaf(a.x, v.x, acc[j]);
                    acc[j] = fmaf(a.y, v.y, acc[j]);
                    acc[j] = fmaf(a.z, v.z, acc[j]);
                    acc[j] = fmaf(a.w, v.w, acc[j]);
                }
            }
#pragma unroll
            for (int j = 0; j < 4; j++)
#pragma unroll
                for (int off = 16; off; off >>= 1)
                    acc[j] += __shfl_xor_sync(0xFFFFFFFFu, acc[j], off);

            // group stats: fixed evaluation order -> deterministic
            float m = fmaxf(fmaxf(acc[0], acc[1]), fmaxf(acc[2], acc[3]));
            float s = __expf(acc[0] - m) + __expf(acc[1] - m)
                    + __expf(acc[2] - m) + __expf(acc[3] - m);

            if (lane == 0) {
                *reinterpret_cast<float4*>(&g_energies[(size_t)b * L + l0]) =
                    make_float4(acc[0], acc[1], acc[2], acc[3]);
                g_cstats[b * NGRP + lgrp] = make_float2(m, s);
            }
        }
    }
    grid_barrier(2);

    // ---------------- P2: combine stats + normalize -----------------------
    // (hid.bias term is constant over l -> cancels in softmax -> omitted.)
    if (blk < B) {
        const int b = blk;
        s_st[tid] = g_cstats[b * NGRP + tid];
        __syncthreads();

        for (int str = 512; str >= 1; str >>= 1) {
            if (tid < str) {
                float2 x = s_st[tid], y = s_st[tid + str];
                float M = fmaxf(x.x, y.x);
                s_st[tid] = make_float2(
                    M, x.y * __expf(x.x - M) + y.y * __expf(y.x - M));
            }
            __syncthreads();
        }
        const float M    = s_st[0].x;
        const float invS = 1.f / s_st[0].y;

#pragma unroll
        for (int k = 0; k < 4; k++) {
            const int idx = tid + NTH * k;
            out[(size_t)b * L + idx] =
                __expf(g_energies[(size_t)b * L + idx] - M) * invS;
        }
    }
}

// ---------------------------------------------------------------------------
// Launch. Inputs (metadata order): hidden [1,B,H], encoder_outputs [L,B,H],
// W [H,H], b [H]. Output: [B,1,L] float32.
// ---------------------------------------------------------------------------
extern "C" void kernel_launch(void* const* d_in, const int* in_sizes, int n_in,
                              void* d_out, int out_size)
{
    const float* hid = (const float*)d_in[0];
    const float* enc = (const float*)d_in[1];
    const float* W   = (const float*)d_in[2];
    // d_in[3] (bias) cancels in softmax -> unused.
    float* out = (float*)d_out;

    static int attr_done = 0;
    if (!attr_done) {
        cudaFuncSetAttribute(k_fused,
                             cudaFuncAttributeMaxDynamicSharedMemorySize,
                             128 * 1024);
        attr_done = 1;
    }

    k_fused<<<GRID, NTH, 128 * 1024>>>(hid, enc, W, out);
}

// round 12
// speedup vs baseline: 1.0091x; 1.0091x over previous
#include <cuda_runtime.h>
#include <math.h>

// Problem constants
#define B 32
#define L 4096
#define H 1024
#define GRID 148            // == SM count -> every block resident in wave 1
#define NTH 1024
#define NWARPS (GRID * 32)  // 4736 warps; 4736 % 32 == 0 -> warp keeps fixed b
#define NGRP (L / 4)        // 1024 groups of 4 rows per b
#define TOTGRP (B * NGRP)   // 32768

// Scratch (device globals — no allocation allowed)
__device__ float    g_vpart[32][B * H];    // 4 MB GEMM partials
__device__ float    g_v[B * H];            // 128 KB  v = hid @ W
__device__ float    g_energies[B * L];     // 512 KB
__device__ float2   g_cstats[B * NGRP];    // per-group (max, sumexp), keyed -> deterministic
__device__ unsigned g_barctr[3];           // monotonic grid-barrier counters (never reset)

// Grid barrier: monotonic counter, safe across graph replays (no reset).
__device__ __forceinline__ void grid_barrier(int site)
{
    __syncthreads();
    if (threadIdx.x == 0) {
        __threadfence();
        unsigned t = atomicAdd(&g_barctr[site], 1u);
        unsigned target = (t / GRID + 1u) * GRID;
        unsigned v;
        do {
            asm volatile("ld.acquire.gpu.u32 %0, [%1];"
                         : "=r"(v) : "l"(&g_barctr[site]));
        } while (v < target);
    }
    __syncthreads();
}

__global__ void __launch_bounds__(NTH, 1)
k_fused(const float* __restrict__ hid, const float* __restrict__ enc,
        const float* __restrict__ W, float* __restrict__ out)
{
    __shared__ float  sh_hid[32][33];   // P0 hid tile (padded)
    __shared__ float2 s_st[NGRP];       // P2 stat tree (8 KB)

    const int tid  = threadIdx.x;
    const int blk  = blockIdx.x;
    const int wid  = tid >> 5;
    const int lane = tid & 31;

    // ---------------- P0a: GEMM partials ----------------------------------
    if (blk < 128) {
        const int g0 = (blk & 31) * 32;                 // g-chunk
        const int h  = (blk >> 5) * 256 + (tid & 255);  // h quarter
        const int b0 = (tid >> 8) * 8;                  // 8-b subgroup

        { // stage hid[b][g0..g0+32] tile (1024 elems, one per thread)
            int bb = tid >> 5, gi = tid & 31;
            sh_hid[bb][gi] = hid[bb * H + g0 + gi];
        }
        __syncthreads();

        float acc[8];
#pragma unroll
        for (int k = 0; k < 8; k++) acc[k] = 0.f;

#pragma unroll 4
        for (int gi = 0; gi < 32; gi++) {
            const float w = W[(size_t)(g0 + gi) * H + h];
#pragma unroll
            for (int k = 0; k < 8; k++)
                acc[k] = fmaf(sh_hid[b0 + k][gi], w, acc[k]);
        }
#pragma unroll
        for (int k = 0; k < 8; k++)
            g_vpart[blk & 31][(size_t)(b0 + k) * H + h] = acc[k];
    }
    grid_barrier(0);

    // ---------------- P0b: deterministic reduce to g_v --------------------
    if (blk < 32) {
        const int i = blk * NTH + tid;
        float s = 0.f;
#pragma unroll
        for (int gc = 0; gc < 32; gc++) s += g_vpart[gc][i];
        g_v[i] = s;
    }
    grid_barrier(1);

    // ---------------- P1: energies + per-group softmax stats --------------
    // Static assignment: group g = gwarp + k*NWARPS; b = wid fixed per warp.
    // v[b] read via __ldg — the warp's 4 KB v row stays L1-resident across
    // its enc stream (no smem carveout -> full L1 + full in-flight capacity).
    {
        const int gwarp = blk * 32 + wid;
        const int b     = wid;                  // == gwarp & 31
        const float4* vb4 = reinterpret_cast<const float4*>(g_v) + b * 256;

        for (int g = gwarp; g < TOTGRP; g += NWARPS) {
            const int lgrp = g >> 5;
            const int l0   = lgrp * 4;

            float acc[4] = {0.f, 0.f, 0.f, 0.f};
#pragma unroll
            for (int j = 0; j < 4; j++) {
                const float4* e4 = reinterpret_cast<const float4*>(
                    enc + ((size_t)(l0 + j) * B + b) * H);
#pragma unroll
                for (int i = 0; i < 8; i++) {
                    float4 a = e4[lane + 32 * i];
                    float4 v = __ldg(vb4 + lane + 32 * i);
                    acc[j] = fmaf(a.x, v.x, acc[j]);
                    acc[j] = fmaf(a.y, v.y, acc[j]);
                    acc[j] = fmaf(a.z, v.z, acc[j]);
                    acc[j] = fmaf(a.w, v.w, acc[j]);
                }
            }
#pragma unroll
            for (int j = 0; j < 4; j++)
#pragma unroll
                for (int off = 16; off; off >>= 1)
                    acc[j] += __shfl_xor_sync(0xFFFFFFFFu, acc[j], off);

            // group stats: fixed evaluation order -> deterministic
            float m = fmaxf(fmaxf(acc[0], acc[1]), fmaxf(acc[2], acc[3]));
            float s = __expf(acc[0] - m) + __expf(acc[1] - m)
                    + __expf(acc[2] - m) + __expf(acc[3] - m);

            if (lane == 0) {
                *reinterpret_cast<float4*>(&g_energies[(size_t)b * L + l0]) =
                    make_float4(acc[0], acc[1], acc[2], acc[3]);
                g_cstats[b * NGRP + lgrp] = make_float2(m, s);
            }
        }
    }
    grid_barrier(2);

    // ---------------- P2: combine stats + normalize -----------------------
    // (hid.bias term is constant over l -> cancels in softmax -> omitted.)
    if (blk < B) {
        const int b = blk;
        s_st[tid] = g_cstats[b * NGRP + tid];
        __syncthreads();

        for (int str = 512; str >= 1; str >>= 1) {
            if (tid < str) {
                float2 x = s_st[tid], y = s_st[tid + str];
                float M = fmaxf(x.x, y.x);
                s_st[tid] = make_float2(
                    M, x.y * __expf(x.x - M) + y.y * __expf(y.x - M));
            }
            __syncthreads();
        }
        const float M    = s_st[0].x;
        const float invS = 1.f / s_st[0].y;

#pragma unroll
        for (int k = 0; k < 4; k++) {
            const int idx = tid + NTH * k;
            out[(size_t)b * L + idx] =
                __expf(g_energies[(size_t)b * L + idx] - M) * invS;
        }
    }
}

// ---------------------------------------------------------------------------
// Launch. Inputs (metadata order): hidden [1,B,H], encoder_outputs [L,B,H],
// W [H,H], b [H]. Output: [B,1,L] float32.
// ---------------------------------------------------------------------------
extern "C" void kernel_launch(void* const* d_in, const int* in_sizes, int n_in,
                              void* d_out, int out_size)
{
    const float* hid = (const float*)d_in[0];
    const float* enc = (const float*)d_in[1];
    const float* W   = (const float*)d_in[2];
    // d_in[3] (bias) cancels in softmax -> unused.
    float* out = (float*)d_out;

    k_fused<<<GRID, NTH>>>(hid, enc, W, out);
}

// round 15
// speedup vs baseline: 1.0277x; 1.0184x over previous
#include <cuda_runtime.h>
#include <math.h>

#define B 32
#define L 4096
#define H 1024
#define NBLK_L (L / 8)       // 512 energy blocks per b
#define G1 128               // K1 grid (all resident)

// Scratch (device globals — no allocation allowed)
__device__ float    g_vpart[32][B * H];     // 4 MB GEMM partials
__device__ float    g_v[B * H];             // 128 KB
__device__ float    g_energies[B * L];      // 512 KB
__device__ float2   g_stats[B * NBLK_L];    // per-block (max, sumexp)
__device__ unsigned g_cnt[B];               // monotonic per-b completion counters
__device__ unsigned g_barctr;               // monotonic K1 barrier counter

// ---------------------------------------------------------------------------
// K1: v = hid @ W in ONE launch. 128 blocks (all resident), internal barrier.
// Phase A: block (gc, hq) computes partials for g-chunk gc, h-quarter hq.
// Phase B: 1 element/thread deterministic reduce.
// ---------------------------------------------------------------------------
__global__ void __launch_bounds__(256, 1)
k_vgemm(const float* __restrict__ hid, const float* __restrict__ W)
{
    __shared__ float sh[32][33];
    const int tid = threadIdx.x;
    const int blk = blockIdx.x;
    const int gc  = blk & 31;            // g-chunk
    const int g0  = gc * 32;
    const int h   = (blk >> 5) * 256 + tid;

    { // stage hid tile: 1024 elems, 256 threads
        for (int i = tid; i < 32 * 32; i += 256)
            sh[i >> 5][i & 31] = hid[(i >> 5) * H + g0 + (i & 31)];
    }
    __syncthreads();

    float acc[32];
#pragma unroll
    for (int b = 0; b < 32; b++) acc[b] = 0.f;

#pragma unroll 4
    for (int gi = 0; gi < 32; gi++) {
        const float w = W[(size_t)(g0 + gi) * H + h];
#pragma unroll
        for (int b = 0; b < 32; b++)
            acc[b] = fmaf(sh[b][gi], w, acc[b]);
    }
#pragma unroll
    for (int b = 0; b < 32; b++)
        g_vpart[gc][(size_t)b * H + h] = acc[b];

    // grid barrier (monotonic, replay-safe)
    __syncthreads();
    if (tid == 0) {
        __threadfence();
        unsigned t = atomicAdd(&g_barctr, 1u);
        unsigned target = (t / G1 + 1u) * G1;
        unsigned v;
        do {
            asm volatile("ld.acquire.gpu.u32 %0, [%1];"
                         : "=r"(v) : "l"(&g_barctr));
        } while (v < target);
    }
    __syncthreads();

    // Phase B: deterministic reduce, 1 element per thread (128*256 = 32768)
    const int i = blk * 256 + tid;
    float s = 0.f;
#pragma unroll
    for (int k = 0; k < 32; k++) s += g_vpart[k][i];
    g_v[i] = s;
}

// ---------------------------------------------------------------------------
// K2: energies (R2-proven shape) + block stats + last-block-per-b norm.
// grid (B, 512), block 256 (8 warps x 1 l). (hid.bias cancels in softmax.)
// ---------------------------------------------------------------------------
__global__ void k_energies(const float* __restrict__ enc, float* __restrict__ out)
{
    __shared__ float4 sv[H / 4];       // 4 KB v[b]
    __shared__ float  s_e[8];
    __shared__ float2 s_st[256];
    __shared__ int    s_last;

    const int b   = blockIdx.x;
    const int ly  = blockIdx.y;
    const int tid = threadIdx.x;
    const int w    = tid >> 5;
    const int lane = tid & 31;

    sv[tid] = reinterpret_cast<const float4*>(g_v + (size_t)b * H)[tid];
    __syncthreads();

    // --- energy dot: one l per warp (proven 6.4 TB/s config) ---
    const int l = ly * 8 + w;
    const float4* e4 = reinterpret_cast<const float4*>(enc + ((size_t)l * B + b) * H);

    float acc = 0.f;
#pragma unroll
    for (int i = 0; i < 8; i++) {
        float4 a = e4[lane + 32 * i];
        float4 v = sv[lane + 32 * i];
        acc = fmaf(a.x, v.x, acc);
        acc = fmaf(a.y, v.y, acc);
        acc = fmaf(a.z, v.z, acc);
        acc = fmaf(a.w, v.w, acc);
    }
#pragma unroll
    for (int off = 16; off; off >>= 1)
        acc += __shfl_xor_sync(0xFFFFFFFFu, acc, off);

    if (lane == 0) {
        g_energies[(size_t)b * L + l] = acc;
        s_e[w] = acc;
    }
    __syncthreads();

    // --- block stats (warp 0, deterministic) ---
    if (w == 0) {
        float e = (lane < 8) ? s_e[lane] : -INFINITY;
        float m = e;
#pragma unroll
        for (int off = 16; off; off >>= 1)
            m = fmaxf(m, __shfl_xor_sync(0xFFFFFFFFu, m, off));
        float s = (lane < 8) ? __expf(e - m) : 0.f;
#pragma unroll
        for (int off = 16; off; off >>= 1)
            s += __shfl_xor_sync(0xFFFFFFFFu, s, off);
        if (lane == 0) g_stats[b * NBLK_L + ly] = make_float2(m, s);
    }
    __syncthreads();

    // --- completion count: last block of this b runs the norm ---
    if (tid == 0) {
        __threadfence();                       // release energies + stats
        unsigned old = atomicAdd(&g_cnt[b], 1u);
        s_last = (((old + 1u) & (NBLK_L - 1u)) == 0u);   // replay-safe
    }
    __syncthreads();
    if (!s_last) return;

    // --- norm (one block per b): combine 512 stats, fixed-order tree ---
    {
        float2 x = g_stats[b * NBLK_L + 2 * tid];
        float2 y = g_stats[b * NBLK_L + 2 * tid + 1];
        float M = fmaxf(x.x, y.x);
        s_st[tid] = make_float2(M, x.y * __expf(x.x - M) + y.y * __expf(y.x - M));
    }
    __syncthreads();
    for (int str = 128; str >= 1; str >>= 1) {
        if (tid < str) {
            float2 x = s_st[tid], y = s_st[tid + str];
            float M = fmaxf(x.x, y.x);
            s_st[tid] = make_float2(M, x.y * __expf(x.x - M) + y.y * __expf(y.x - M));
        }
        __syncthreads();
    }
    const float M    = s_st[0].x;
    const float invS = 1.f / s_st[0].y;

#pragma unroll
    for (int k = 0; k < 16; k++) {
        const int idx = tid + 256 * k;
        out[(size_t)b * L + idx] =
            __expf(g_energies[(size_t)b * L + idx] - M) * invS;
    }
}

// ---------------------------------------------------------------------------
// Launch. Inputs (metadata order): hidden [1,B,H], encoder_outputs [L,B,H],
// W [H,H], b [H]. Output: [B,1,L] float32.
// ---------------------------------------------------------------------------
extern "C" void kernel_launch(void* const* d_in, const int* in_sizes, int n_in,
                              void* d_out, int out_size)
{
    const float* hid = (const float*)d_in[0];
    const float* enc = (const float*)d_in[1];
    const float* W   = (const float*)d_in[2];
    // d_in[3] (bias) cancels in softmax -> unused.
    float* out = (float*)d_out;

    k_vgemm<<<G1, 256>>>(hid, W);
    k_energies<<<dim3(B, NBLK_L), 256>>>(enc, out);
}

// round 16
// speedup vs baseline: 1.2147x; 1.1820x over previous
#include <cuda_runtime.h>
#include <math.h>

// Problem constants
#define B 32
#define L 4096
#define H 1024
#define GCHUNKS 32

// Scratch (device globals — no allocation allowed)
__device__ float g_vpart[GCHUNKS][B * H];   // 4 MB partials for v = hid @ W
__device__ float g_v[B * H];                // 128 KB
__device__ float g_energies[B * L];         // 512 KB

// ---------------------------------------------------------------------------
// Kernel 1: partial v[b,h] = sum_{g in chunk} hid[b,g] * W[g,h]
// grid = (H/256, GCHUNKS), block = 256. (R2-proven)
// ---------------------------------------------------------------------------
__global__ void k_vpart(const float* __restrict__ hid, const float* __restrict__ W)
{
    __shared__ float sh[B][32];
    const int h  = blockIdx.x * 256 + threadIdx.x;
    const int g0 = blockIdx.y * 32;

    for (int i = threadIdx.x; i < B * 32; i += 256) {
        int b = i >> 5, gi = i & 31;
        sh[b][gi] = hid[b * H + g0 + gi];
    }
    __syncthreads();

    float acc[B];
#pragma unroll
    for (int b = 0; b < B; b++) acc[b] = 0.f;

#pragma unroll
    for (int gi = 0; gi < 32; gi += 4) {
        const float w0 = W[(size_t)(g0 + gi + 0) * H + h];
        const float w1 = W[(size_t)(g0 + gi + 1) * H + h];
        const float w2 = W[(size_t)(g0 + gi + 2) * H + h];
        const float w3 = W[(size_t)(g0 + gi + 3) * H + h];
#pragma unroll
        for (int b = 0; b < B; b++) {
            float4 hv = *reinterpret_cast<const float4*>(&sh[b][gi]);
            acc[b] = fmaf(hv.x, w0, acc[b]);
            acc[b] = fmaf(hv.y, w1, acc[b]);
            acc[b] = fmaf(hv.z, w2, acc[b]);
            acc[b] = fmaf(hv.w, w3, acc[b]);
        }
    }
#pragma unroll
    for (int b = 0; b < B; b++)
        g_vpart[blockIdx.y][b * H + h] = acc[b];
}

// ---------------------------------------------------------------------------
// Kernel 2: deterministic reduce of partials (R2-proven)
// ---------------------------------------------------------------------------
__global__ void k_vreduce()
{
    const int i = blockIdx.x * blockDim.x + threadIdx.x;
    float s = 0.f;
#pragma unroll
    for (int gc = 0; gc < GCHUNKS; gc++) s += g_vpart[gc][i];
    g_v[i] = s;
}

// ---------------------------------------------------------------------------
// Kernel 3 (HBM-bound, MINIMAL): energies[b,l] = v[b] . enc[l,b]
// R2-exact shape: grid (B, L/8), 256 thr, v staged in 4 KB smem, 1 l/warp.
// Single delta: enc loads use __ldcs (evict-first; enc is read exactly once).
// NO stats, NO atomics, NO fences in this kernel.
// ---------------------------------------------------------------------------
__global__ void k_energies(const float* __restrict__ enc)
{
    __shared__ float4 sv[H / 4];             // 4 KB: v[b]
    const int b = blockIdx.x;

    sv[threadIdx.x] = reinterpret_cast<const float4*>(g_v + (size_t)b * H)[threadIdx.x];
    __syncthreads();

    const int w    = threadIdx.x >> 5;
    const int lane = threadIdx.x & 31;
    const int l    = blockIdx.y * 8 + w;

    const float4* e4 = reinterpret_cast<const float4*>(enc + ((size_t)l * B + b) * H);

    float acc = 0.f;
#pragma unroll
    for (int i = 0; i < 8; i++) {
        float4 a = __ldcs(e4 + lane + 32 * i);   // streaming, evict-first
        float4 v = sv[lane + 32 * i];
        acc = fmaf(a.x, v.x, acc);
        acc = fmaf(a.y, v.y, acc);
        acc = fmaf(a.z, v.z, acc);
        acc = fmaf(a.w, v.w, acc);
    }
#pragma unroll
    for (int off = 16; off; off >>= 1)
        acc += __shfl_xor_sync(0xFFFFFFFFu, acc, off);

    if (lane == 0) g_energies[(size_t)b * L + l] = acc;
}

// ---------------------------------------------------------------------------
// Kernel 4: row softmax over L, one block (512 thr) per b — the 5.09 µs
// R1-measured variant. (hid.bias cancels in softmax -> omitted.)
// ---------------------------------------------------------------------------
__global__ void k_softmax(float* __restrict__ out)
{
    const int b   = blockIdx.x;
    const int tid = threadIdx.x;            // blockDim = 512
    const float* e = &g_energies[(size_t)b * L];

    float vals[8];
    float m = -INFINITY;
#pragma unroll
    for (int i = 0; i < 8; i++) {
        vals[i] = e[tid + i * 512];
        m = fmaxf(m, vals[i]);
    }

    __shared__ float red[16];
#pragma unroll
    for (int off = 16; off; off >>= 1)
        m = fmaxf(m, __shfl_xor_sync(0xFFFFFFFFu, m, off));
    if ((tid & 31) == 0) red[tid >> 5] = m;
    __syncthreads();
    if (tid < 32) {
        float t = (tid < 16) ? red[tid] : -INFINITY;
#pragma unroll
        for (int off = 8; off; off >>= 1)
            t = fmaxf(t, __shfl_xor_sync(0xFFFFFFFFu, t, off));
        if (tid == 0) red[0] = t;
    }
    __syncthreads();
    m = red[0];
    __syncthreads();

    float s = 0.f;
#pragma unroll
    for (int i = 0; i < 8; i++) {
        vals[i] = __expf(vals[i] - m);
        s += vals[i];
    }
#pragma unroll
    for (int off = 16; off; off >>= 1)
        s += __shfl_xor_sync(0xFFFFFFFFu, s, off);
    if ((tid & 31) == 0) red[tid >> 5] = s;
    __syncthreads();
    if (tid < 32) {
        float t = (tid < 16) ? red[tid] : 0.f;
#pragma unroll
        for (int off = 8; off; off >>= 1)
            t += __shfl_xor_sync(0xFFFFFFFFu, t, off);
        if (tid == 0) red[0] = t;
    }
    __syncthreads();
    const float inv = 1.f / red[0];

#pragma unroll
    for (int i = 0; i < 8; i++)
        out[(size_t)b * L + tid + i * 512] = vals[i] * inv;
}

// ---------------------------------------------------------------------------
// Launch. Inputs (metadata order): hidden [1,B,H], encoder_outputs [L,B,H],
// W [H,H], b [H]. Output: [B,1,L] float32.
// ---------------------------------------------------------------------------
extern "C" void kernel_launch(void* const* d_in, const int* in_sizes, int n_in,
                              void* d_out, int out_size)
{
    const float* hid = (const float*)d_in[0];
    const float* enc = (const float*)d_in[1];
    const float* W   = (const float*)d_in[2];
    // d_in[3] (bias) cancels in softmax -> unused.
    float* out = (float*)d_out;

    k_vpart<<<dim3(H / 256, GCHUNKS), 256>>>(hid, W);
    k_vreduce<<<(B * H) / 256, 256>>>();
    k_energies<<<dim3(B, L / 8), 256>>>(enc);
    k_softmax<<<B, 512>>>(out);
}